// round 4
// baseline (speedup 1.0000x reference)
#include <cuda_runtime.h>
#include <cuda_bf16.h>
#include <cstdint>

// Problem constants
#define BB 2
#define NN 2048
#define HH 16
#define DH 64
#define DD 1024          // HH*DH
#define D3 3072          // 3*DD
#define MM 4096          // BB*NN

// Scratch for QKV, laid out [part(q/k/v)][B][H][N][Dh]
__device__ float g_qkv[3u * BB * HH * NN * DH];

// ---------------------------------------------------------------------------
// Kernel 1: QKV GEMM  C[4096,3072] = X[4096,1024] @ W[1024,3072]
// 128x128x16 tiles, 256 threads, 8x8 per-thread, double-buffered smem.
// Epilogue scatters into g_qkv per-head layout.
// ---------------------------------------------------------------------------
__global__ __launch_bounds__(256, 2)
void qkv_gemm_kernel(const float* __restrict__ X, const float* __restrict__ W)
{
    __shared__ float As[2][16][132];   // A transposed [k][m], padded ld=132
    __shared__ float Bs[2][16][128];   // B natural   [k][n]

    const int bx = blockIdx.x;         // 0..23 over N(3072)
    const int by = blockIdx.y;         // 0..31 over M(4096)
    const int tid = threadIdx.x;
    const int tx = tid & 15;           // col group
    const int ty = tid >> 4;           // row group

    // load mapping
    const int rowA = tid >> 2;         // 0..63
    const int k4A  = (tid & 3) * 4;    // 0,4,8,12
    const int rowB = tid >> 5;         // 0..7
    const int c4B  = (tid & 31) * 4;   // 0..124

    const float* Ag = X + (size_t)(by * 128) * DD;
    const float* Bg = W + bx * 128;

    float acc[8][8];
#pragma unroll
    for (int i = 0; i < 8; ++i)
#pragma unroll
        for (int j = 0; j < 8; ++j) acc[i][j] = 0.0f;

    // ---- prologue: tile 0 ----
    {
        float4 a0 = *(const float4*)(Ag + (size_t)rowA * DD + k4A);
        float4 a1 = *(const float4*)(Ag + (size_t)(rowA + 64) * DD + k4A);
        float4 b0 = *(const float4*)(Bg + (size_t)rowB * D3 + c4B);
        float4 b1 = *(const float4*)(Bg + (size_t)(rowB + 8) * D3 + c4B);
        As[0][k4A + 0][rowA] = a0.x; As[0][k4A + 1][rowA] = a0.y;
        As[0][k4A + 2][rowA] = a0.z; As[0][k4A + 3][rowA] = a0.w;
        As[0][k4A + 0][rowA + 64] = a1.x; As[0][k4A + 1][rowA + 64] = a1.y;
        As[0][k4A + 2][rowA + 64] = a1.z; As[0][k4A + 3][rowA + 64] = a1.w;
        *(float4*)&Bs[0][rowB][c4B]     = b0;
        *(float4*)&Bs[0][rowB + 8][c4B] = b1;
    }
    __syncthreads();

    for (int t = 0; t < 64; ++t) {
        const int s = t & 1;
        float4 a0, a1, b0, b1;
        if (t < 63) {
            const int k0 = (t + 1) * 16;
            a0 = *(const float4*)(Ag + (size_t)rowA * DD + k0 + k4A);
            a1 = *(const float4*)(Ag + (size_t)(rowA + 64) * DD + k0 + k4A);
            b0 = *(const float4*)(Bg + (size_t)(k0 + rowB) * D3 + c4B);
            b1 = *(const float4*)(Bg + (size_t)(k0 + rowB + 8) * D3 + c4B);
        }
#pragma unroll
        for (int k = 0; k < 16; ++k) {
            float4 af0 = *(const float4*)&As[s][k][ty * 8];
            float4 af1 = *(const float4*)&As[s][k][ty * 8 + 4];
            float4 bf0 = *(const float4*)&Bs[s][k][tx * 8];
            float4 bf1 = *(const float4*)&Bs[s][k][tx * 8 + 4];
            float av[8] = {af0.x, af0.y, af0.z, af0.w, af1.x, af1.y, af1.z, af1.w};
            float bv[8] = {bf0.x, bf0.y, bf0.z, bf0.w, bf1.x, bf1.y, bf1.z, bf1.w};
#pragma unroll
            for (int i = 0; i < 8; ++i)
#pragma unroll
                for (int j = 0; j < 8; ++j)
                    acc[i][j] = fmaf(av[i], bv[j], acc[i][j]);
        }
        if (t < 63) {
            const int ss = s ^ 1;
            As[ss][k4A + 0][rowA] = a0.x; As[ss][k4A + 1][rowA] = a0.y;
            As[ss][k4A + 2][rowA] = a0.z; As[ss][k4A + 3][rowA] = a0.w;
            As[ss][k4A + 0][rowA + 64] = a1.x; As[ss][k4A + 1][rowA + 64] = a1.y;
            As[ss][k4A + 2][rowA + 64] = a1.z; As[ss][k4A + 3][rowA + 64] = a1.w;
            *(float4*)&Bs[ss][rowB][c4B]     = b0;
            *(float4*)&Bs[ss][rowB + 8][c4B] = b1;
            __syncthreads();
        }
    }

    // ---- epilogue: scatter into g_qkv[part][b][h][n][dh] ----
    const int part = (bx * 128) >> 10;          // 0/1/2 (128-col block never straddles)
    const int rem0 = (bx * 128) & 1023;
    const int colh = rem0 + tx * 8;             // 8 cols stay inside one head
    const int h    = colh >> 6;
    const int dh   = colh & 63;
    const int b    = (by * 128) >> 11;
    const int n0   = ((by * 128) & 2047) + ty * 8;

    float* dst = g_qkv + (size_t)(((part * BB + b) * HH + h)) * NN * DH;
#pragma unroll
    for (int i = 0; i < 8; ++i) {
        float4 w0 = make_float4(acc[i][0], acc[i][1], acc[i][2], acc[i][3]);
        float4 w1 = make_float4(acc[i][4], acc[i][5], acc[i][6], acc[i][7]);
        *(float4*)(dst + (size_t)(n0 + i) * DH + dh)     = w0;
        *(float4*)(dst + (size_t)(n0 + i) * DH + dh + 4) = w1;
    }
}

// ---------------------------------------------------------------------------
// Kernel 2: causal flash attention, fp32.
// Block = (b, h, 64-query tile). 128 threads: ty=tid/8 (16 row groups of 4),
// tx=tid%8 (8 col groups of 8). S tile 64x64, online softmax, P*V.
// Smem: Qt[64][65] (d-major), KP[64][65] (K d-major, reused for P r-major),
//       Vs[64][64] (natural). Dynamic smem = 49664 B.
// ---------------------------------------------------------------------------
#define LDT 65
#define ATT_SMEM_BYTES ((2 * 64 * LDT + 64 * 64) * 4)

__global__ __launch_bounds__(128, 4)
void attn_kernel(float* __restrict__ out)
{
    extern __shared__ float sm[];
    float* Qt = sm;                 // [d][r], ld LDT
    float* KP = sm + 64 * LDT;      // K: [d][c] ld LDT; later P: [r][k] ld LDT
    float* Vs = sm + 2 * 64 * LDT;  // [k][d], ld 64

    const int qb = gridDim.x - 1 - blockIdx.x;   // heavy tiles first
    const int h  = blockIdx.y;
    const int b  = blockIdx.z;
    const int tid = threadIdx.x;
    const int tx = tid & 7;
    const int ty = tid >> 3;

    const float* Qg = g_qkv + (size_t)(((0 * BB + b) * HH + h)) * NN * DH + (size_t)qb * 64 * DH;
    const float* Kg = g_qkv + (size_t)(((1 * BB + b) * HH + h)) * NN * DH;
    const float* Vg = g_qkv + (size_t)(((2 * BB + b) * HH + h)) * NN * DH;

    // load Q tile transposed into Qt
#pragma unroll
    for (int it = 0; it < 8; ++it) {
        int idx = it * 128 + tid;          // float4 index, 0..1023
        int r   = idx >> 4;
        int d4  = (idx & 15) << 2;
        float4 v = *(const float4*)(Qg + (size_t)r * DH + d4);
        Qt[(d4 + 0) * LDT + r] = v.x;
        Qt[(d4 + 1) * LDT + r] = v.y;
        Qt[(d4 + 2) * LDT + r] = v.z;
        Qt[(d4 + 3) * LDT + r] = v.w;
    }

    float o[4][8];
    float m_i[4], l_i[4];
#pragma unroll
    for (int i = 0; i < 4; ++i) {
        m_i[i] = -1e30f; l_i[i] = 0.0f;
#pragma unroll
        for (int j = 0; j < 8; ++j) o[i][j] = 0.0f;
    }

    const int nkt = qb + 1;
    for (int kt = 0; kt < nkt; ++kt) {
        __syncthreads();   // prior PV reads of KP/Vs done before overwrite
        // load K (transposed) and V (natural)
#pragma unroll
        for (int it = 0; it < 8; ++it) {
            int idx = it * 128 + tid;
            int r   = idx >> 4;
            int d4  = (idx & 15) << 2;
            float4 kv = *(const float4*)(Kg + (size_t)(kt * 64 + r) * DH + d4);
            KP[(d4 + 0) * LDT + r] = kv.x;
            KP[(d4 + 1) * LDT + r] = kv.y;
            KP[(d4 + 2) * LDT + r] = kv.z;
            KP[(d4 + 3) * LDT + r] = kv.w;
            float4 vv = *(const float4*)(Vg + (size_t)(kt * 64 + r) * DH + d4);
            *(float4*)(Vs + r * 64 + d4) = vv;
        }
        __syncthreads();

        // S = Q @ K^T (register tile 4x8)
        float s[4][8];
#pragma unroll
        for (int i = 0; i < 4; ++i)
#pragma unroll
            for (int j = 0; j < 8; ++j) s[i][j] = 0.0f;

#pragma unroll 8
        for (int d = 0; d < 64; ++d) {
            float qr[4], kr[8];
#pragma unroll
            for (int i = 0; i < 4; ++i) qr[i] = Qt[d * LDT + ty * 4 + i];
#pragma unroll
            for (int j = 0; j < 8; ++j) kr[j] = KP[d * LDT + tx * 8 + j];
#pragma unroll
            for (int i = 0; i < 4; ++i)
#pragma unroll
                for (int j = 0; j < 8; ++j)
                    s[i][j] = fmaf(qr[i], kr[j], s[i][j]);
        }

        // scale + causal mask (only diagonal tile needs masking)
        const float sc = 0.125f;   // 1/sqrt(64)
        const bool diag = (kt == qb);
#pragma unroll
        for (int i = 0; i < 4; ++i)
#pragma unroll
            for (int j = 0; j < 8; ++j) {
                float v = s[i][j] * sc;
                if (diag && (tx * 8 + j) > (ty * 4 + i)) v = -1e30f;
                s[i][j] = v;
            }

        // online softmax (row = ty*4+i shared by the 8 tx lanes)
        float corr[4];
#pragma unroll
        for (int i = 0; i < 4; ++i) {
            float mx = s[i][0];
#pragma unroll
            for (int j = 1; j < 8; ++j) mx = fmaxf(mx, s[i][j]);
            mx = fmaxf(mx, __shfl_xor_sync(0xffffffffu, mx, 1));
            mx = fmaxf(mx, __shfl_xor_sync(0xffffffffu, mx, 2));
            mx = fmaxf(mx, __shfl_xor_sync(0xffffffffu, mx, 4));
            float mnew = fmaxf(m_i[i], mx);
            corr[i] = __expf(m_i[i] - mnew);
            m_i[i] = mnew;
            float rs = 0.0f;
#pragma unroll
            for (int j = 0; j < 8; ++j) {
                float p = __expf(s[i][j] - mnew);
                s[i][j] = p;
                rs += p;
            }
            rs += __shfl_xor_sync(0xffffffffu, rs, 1);
            rs += __shfl_xor_sync(0xffffffffu, rs, 2);
            rs += __shfl_xor_sync(0xffffffffu, rs, 4);
            l_i[i] = l_i[i] * corr[i] + rs;
#pragma unroll
            for (int j = 0; j < 8; ++j) o[i][j] *= corr[i];
        }

        __syncthreads();   // done reading KP as K
        // write P into KP buffer, layout [r][k] ld LDT
#pragma unroll
        for (int i = 0; i < 4; ++i)
#pragma unroll
            for (int j = 0; j < 8; ++j)
                KP[(ty * 4 + i) * LDT + tx * 8 + j] = s[i][j];
        __syncthreads();

        // O += P @ V
#pragma unroll 8
        for (int k = 0; k < 64; ++k) {
            float pr[4];
#pragma unroll
            for (int i = 0; i < 4; ++i) pr[i] = KP[(ty * 4 + i) * LDT + k];
            float4 v0 = *(const float4*)(Vs + k * 64 + tx * 8);
            float4 v1 = *(const float4*)(Vs + k * 64 + tx * 8 + 4);
#pragma unroll
            for (int i = 0; i < 4; ++i) {
                o[i][0] = fmaf(pr[i], v0.x, o[i][0]);
                o[i][1] = fmaf(pr[i], v0.y, o[i][1]);
                o[i][2] = fmaf(pr[i], v0.z, o[i][2]);
                o[i][3] = fmaf(pr[i], v0.w, o[i][3]);
                o[i][4] = fmaf(pr[i], v1.x, o[i][4]);
                o[i][5] = fmaf(pr[i], v1.y, o[i][5]);
                o[i][6] = fmaf(pr[i], v1.z, o[i][6]);
                o[i][7] = fmaf(pr[i], v1.w, o[i][7]);
            }
        }
    }

    // epilogue: out[b][n][h*64 + d]
#pragma unroll
    for (int i = 0; i < 4; ++i) {
        float inv = 1.0f / l_i[i];
        int qr = qb * 64 + ty * 4 + i;
        float4 r0 = make_float4(o[i][0] * inv, o[i][1] * inv, o[i][2] * inv, o[i][3] * inv);
        float4 r1 = make_float4(o[i][4] * inv, o[i][5] * inv, o[i][6] * inv, o[i][7] * inv);
        float* dst = out + (size_t)(b * NN + qr) * DD + h * DH + tx * 8;
        *(float4*)(dst)     = r0;
        *(float4*)(dst + 4) = r1;
    }
}

// ---------------------------------------------------------------------------
extern "C" void kernel_launch(void* const* d_in, const int* in_sizes, int n_in,
                              void* d_out, int out_size)
{
    const float* x = (const float*)d_in[0];   // [2,2048,1024] fp32
    const float* w = (const float*)d_in[1];   // [1024,3072] fp32
    float* out = (float*)d_out;               // [2,2048,1024] fp32
    (void)in_sizes; (void)n_in; (void)out_size;

    // QKV projection into per-head scratch
    dim3 g1(D3 / 128, MM / 128);   // (24, 32)
    qkv_gemm_kernel<<<g1, 256>>>(x, w);

    // causal attention
    cudaFuncSetAttribute(attn_kernel,
                         cudaFuncAttributeMaxDynamicSharedMemorySize,
                         ATT_SMEM_BYTES);
    dim3 g2(NN / 64, HH, BB);      // (32, 16, 2)
    attn_kernel<<<g2, 128, ATT_SMEM_BYTES>>>(out);
}

// round 5
// speedup vs baseline: 1.0146x; 1.0146x over previous
#include <cuda_runtime.h>
#include <cuda_bf16.h>
#include <cstdint>

// Problem constants
#define BB 2
#define NN 2048
#define HH 16
#define DH 64
#define DD 1024          // HH*DH
#define D3 3072          // 3*DD
#define MM 4096          // BB*NN

// Scratch for QKV, laid out [part(q/k/v)][B][H][N][Dh]
__device__ float g_qkv[3u * BB * HH * NN * DH];

// ---------------------------------------------------------------------------
// Kernel 1: QKV GEMM  C[4096,3072] = X[4096,1024] @ W[1024,3072]
// 128x128x16 tiles, 256 threads (8 warps as 4x2, 32x64 per warp, 8x8/thread),
// double-buffered smem. Epilogue scatters into g_qkv per-head layout.
// ---------------------------------------------------------------------------
__global__ __launch_bounds__(256, 2)
void qkv_gemm_kernel(const float* __restrict__ X, const float* __restrict__ W)
{
    __shared__ float As[2][16][132];   // A transposed [k][m], padded ld=132
    __shared__ float Bs[2][16][128];   // B natural   [k][n]

    const int bx = blockIdx.x;         // 0..23 over N(3072)
    const int by = blockIdx.y;         // 0..31 over M(4096)
    const int tid = threadIdx.x;

    // warp-tiled compute mapping: warps 4(rows) x 2(cols), lanes 4(rows) x 8(cols)
    const int wid  = tid >> 5;
    const int wm   = wid & 3;
    const int wn   = wid >> 2;
    const int lane = tid & 31;
    const int lr   = lane >> 3;
    const int lc   = lane & 7;
    const int row0 = wm * 32 + lr * 8;
    const int col0 = wn * 64 + lc * 8;

    // gmem load mapping
    const int rowA = tid >> 2;         // 0..63
    const int k4A  = (tid & 3) * 4;    // 0,4,8,12
    const int rowB = tid >> 5;         // 0..7
    const int c4B  = (tid & 31) * 4;   // 0..124

    const float* Ag = X + (size_t)(by * 128) * DD;
    const float* Bg = W + bx * 128;

    float acc[8][8];
#pragma unroll
    for (int i = 0; i < 8; ++i)
#pragma unroll
        for (int j = 0; j < 8; ++j) acc[i][j] = 0.0f;

    // ---- prologue: tile 0 ----
    {
        float4 a0 = *(const float4*)(Ag + (size_t)rowA * DD + k4A);
        float4 a1 = *(const float4*)(Ag + (size_t)(rowA + 64) * DD + k4A);
        float4 b0 = *(const float4*)(Bg + (size_t)rowB * D3 + c4B);
        float4 b1 = *(const float4*)(Bg + (size_t)(rowB + 8) * D3 + c4B);
        As[0][k4A + 0][rowA] = a0.x; As[0][k4A + 1][rowA] = a0.y;
        As[0][k4A + 2][rowA] = a0.z; As[0][k4A + 3][rowA] = a0.w;
        As[0][k4A + 0][rowA + 64] = a1.x; As[0][k4A + 1][rowA + 64] = a1.y;
        As[0][k4A + 2][rowA + 64] = a1.z; As[0][k4A + 3][rowA + 64] = a1.w;
        *(float4*)&Bs[0][rowB][c4B]     = b0;
        *(float4*)&Bs[0][rowB + 8][c4B] = b1;
    }
    __syncthreads();

    for (int t = 0; t < 64; ++t) {
        const int s = t & 1;
        float4 a0, a1, b0, b1;
        if (t < 63) {
            const int k0 = (t + 1) * 16;
            a0 = *(const float4*)(Ag + (size_t)rowA * DD + k0 + k4A);
            a1 = *(const float4*)(Ag + (size_t)(rowA + 64) * DD + k0 + k4A);
            b0 = *(const float4*)(Bg + (size_t)(k0 + rowB) * D3 + c4B);
            b1 = *(const float4*)(Bg + (size_t)(k0 + rowB + 8) * D3 + c4B);
        }
#pragma unroll
        for (int k = 0; k < 16; ++k) {
            float4 af0 = *(const float4*)&As[s][k][row0];
            float4 af1 = *(const float4*)&As[s][k][row0 + 4];
            float4 bf0 = *(const float4*)&Bs[s][k][col0];
            float4 bf1 = *(const float4*)&Bs[s][k][col0 + 4];
            float av[8] = {af0.x, af0.y, af0.z, af0.w, af1.x, af1.y, af1.z, af1.w};
            float bv[8] = {bf0.x, bf0.y, bf0.z, bf0.w, bf1.x, bf1.y, bf1.z, bf1.w};
#pragma unroll
            for (int i = 0; i < 8; ++i)
#pragma unroll
                for (int j = 0; j < 8; ++j)
                    acc[i][j] = fmaf(av[i], bv[j], acc[i][j]);
        }
        if (t < 63) {
            const int ss = s ^ 1;
            As[ss][k4A + 0][rowA] = a0.x; As[ss][k4A + 1][rowA] = a0.y;
            As[ss][k4A + 2][rowA] = a0.z; As[ss][k4A + 3][rowA] = a0.w;
            As[ss][k4A + 0][rowA + 64] = a1.x; As[ss][k4A + 1][rowA + 64] = a1.y;
            As[ss][k4A + 2][rowA + 64] = a1.z; As[ss][k4A + 3][rowA + 64] = a1.w;
            *(float4*)&Bs[ss][rowB][c4B]     = b0;
            *(float4*)&Bs[ss][rowB + 8][c4B] = b1;
            __syncthreads();
        }
    }

    // ---- epilogue: scatter into g_qkv[part][b][h][n][dh] ----
    const int part = (bx * 128) >> 10;          // 0/1/2 (128-col block never straddles)
    const int rem0 = (bx * 128) & 1023;
    const int colh = rem0 + col0;               // 8 cols stay inside one head
    const int h    = colh >> 6;
    const int dh   = colh & 63;
    const int b    = (by * 128) >> 11;
    const int n0   = ((by * 128) & 2047) + row0;

    float* dst = g_qkv + (size_t)(((part * BB + b) * HH + h)) * NN * DH;
#pragma unroll
    for (int i = 0; i < 8; ++i) {
        float4 w0 = make_float4(acc[i][0], acc[i][1], acc[i][2], acc[i][3]);
        float4 w1 = make_float4(acc[i][4], acc[i][5], acc[i][6], acc[i][7]);
        *(float4*)(dst + (size_t)(n0 + i) * DH + dh)     = w0;
        *(float4*)(dst + (size_t)(n0 + i) * DH + dh + 4) = w1;
    }
}

// ---------------------------------------------------------------------------
// Kernel 2: causal flash attention, fp32, all-vectorized smem.
// Block = (b, h, 64-query tile). 128 threads: ty=tid/8 (row groups of 4),
// tx=tid%8 (col groups of 8). Natural row-major Q/K/P with per-row XOR quad
// swizzle s(r) = (r&15)^((r>>3)&7); V natural unswizzled.
// Smem: Qs[64][64], Ks[64][64] (reused as P), Vs[64][64] = 48 KiB dynamic.
// ---------------------------------------------------------------------------
#define ATT_SMEM_BYTES (3 * 64 * 64 * 4)

__device__ __forceinline__ int swz(int row) {
    return (row & 15) ^ ((row >> 3) & 7);
}

__global__ __launch_bounds__(128, 4)
void attn_kernel(float* __restrict__ out)
{
    extern __shared__ float sm[];
    float* Qs = sm;            // [r][d], row-swizzled quads
    float* Ks = sm + 4096;     // K: [c][d] swizzled; later P: [r][k] swizzled
    float* Vs = sm + 8192;     // [k][d], natural

    const int qb = gridDim.x - 1 - blockIdx.x;   // heavy tiles first
    const int h  = blockIdx.y;
    const int b  = blockIdx.z;
    const int tid = threadIdx.x;
    const int tx = tid & 7;
    const int ty = tid >> 3;

    const float* Qg = g_qkv + (size_t)(((0 * BB + b) * HH + h)) * NN * DH + (size_t)qb * 64 * DH;
    const float* Kg = g_qkv + (size_t)(((1 * BB + b) * HH + h)) * NN * DH;
    const float* Vg = g_qkv + (size_t)(((2 * BB + b) * HH + h)) * NN * DH;

    // per-thread row sets + swizzle constants
    int rq[4], swQ[4], swK[8];
#pragma unroll
    for (int i = 0; i < 4; ++i) { rq[i] = ty * 4 + i; swQ[i] = swz(rq[i]); }
#pragma unroll
    for (int j = 0; j < 8; ++j) swK[j] = swz(tx * 8 + j);

    // load Q tile (prescaled by 1/sqrt(Dh)), row-swizzled float4 stores
#pragma unroll
    for (int it = 0; it < 8; ++it) {
        int idx = it * 128 + tid;          // float4 index, 0..1023
        int r   = idx >> 4;
        int qd  = idx & 15;
        float4 v = *(const float4*)(Qg + (size_t)r * DH + qd * 4);
        v.x *= 0.125f; v.y *= 0.125f; v.z *= 0.125f; v.w *= 0.125f;
        *(float4*)&Qs[r * 64 + ((qd ^ swz(r)) << 2)] = v;
    }

    float o[4][8];
    float m_i[4], l_i[4];
#pragma unroll
    for (int i = 0; i < 4; ++i) {
        m_i[i] = -1e30f; l_i[i] = 0.0f;
#pragma unroll
        for (int j = 0; j < 8; ++j) o[i][j] = 0.0f;
    }

    const int nkt = qb + 1;
    for (int kt = 0; kt < nkt; ++kt) {
        __syncthreads();   // prior PV reads of Ks(P)/Vs done; Q store visible (kt=0)
        // load K (swizzled) and V (natural)
#pragma unroll
        for (int it = 0; it < 8; ++it) {
            int idx = it * 128 + tid;
            int r   = idx >> 4;
            int qd  = idx & 15;
            float4 kv = *(const float4*)(Kg + (size_t)(kt * 64 + r) * DH + qd * 4);
            *(float4*)&Ks[r * 64 + ((qd ^ swz(r)) << 2)] = kv;
            float4 vv = *(const float4*)(Vg + (size_t)(kt * 64 + r) * DH + qd * 4);
            *(float4*)&Vs[r * 64 + qd * 4] = vv;
        }
        __syncthreads();

        // S = Q @ K^T (register tile 4x8), vectorized swizzled reads
        float s[4][8];
#pragma unroll
        for (int i = 0; i < 4; ++i)
#pragma unroll
            for (int j = 0; j < 8; ++j) s[i][j] = 0.0f;

#pragma unroll 4
        for (int qd = 0; qd < 16; ++qd) {
            float4 qv[4];
#pragma unroll
            for (int i = 0; i < 4; ++i)
                qv[i] = *(const float4*)&Qs[rq[i] * 64 + ((qd ^ swQ[i]) << 2)];
#pragma unroll
            for (int half = 0; half < 2; ++half) {
                float4 kv[4];
#pragma unroll
                for (int jj = 0; jj < 4; ++jj) {
                    int j = half * 4 + jj;
                    kv[jj] = *(const float4*)&Ks[(tx * 8 + j) * 64 + ((qd ^ swK[j]) << 2)];
                }
#pragma unroll
                for (int i = 0; i < 4; ++i)
#pragma unroll
                    for (int jj = 0; jj < 4; ++jj) {
                        int j = half * 4 + jj;
                        s[i][j] = fmaf(qv[i].x, kv[jj].x, s[i][j]);
                        s[i][j] = fmaf(qv[i].y, kv[jj].y, s[i][j]);
                        s[i][j] = fmaf(qv[i].z, kv[jj].z, s[i][j]);
                        s[i][j] = fmaf(qv[i].w, kv[jj].w, s[i][j]);
                    }
            }
        }

        // causal mask (only diagonal tile needs masking); Q already prescaled
        if (kt == qb) {
#pragma unroll
            for (int i = 0; i < 4; ++i)
#pragma unroll
                for (int j = 0; j < 8; ++j)
                    if ((tx * 8 + j) > (ty * 4 + i)) s[i][j] = -1e30f;
        }

        // online softmax (row = ty*4+i shared by the 8 tx lanes)
        float corr[4];
#pragma unroll
        for (int i = 0; i < 4; ++i) {
            float mx = s[i][0];
#pragma unroll
            for (int j = 1; j < 8; ++j) mx = fmaxf(mx, s[i][j]);
            mx = fmaxf(mx, __shfl_xor_sync(0xffffffffu, mx, 1));
            mx = fmaxf(mx, __shfl_xor_sync(0xffffffffu, mx, 2));
            mx = fmaxf(mx, __shfl_xor_sync(0xffffffffu, mx, 4));
            float mnew = fmaxf(m_i[i], mx);
            corr[i] = __expf(m_i[i] - mnew);
            m_i[i] = mnew;
            float rs = 0.0f;
#pragma unroll
            for (int j = 0; j < 8; ++j) {
                float p = __expf(s[i][j] - mnew);
                s[i][j] = p;
                rs += p;
            }
            rs += __shfl_xor_sync(0xffffffffu, rs, 1);
            rs += __shfl_xor_sync(0xffffffffu, rs, 2);
            rs += __shfl_xor_sync(0xffffffffu, rs, 4);
            l_i[i] = l_i[i] * corr[i] + rs;
#pragma unroll
            for (int j = 0; j < 8; ++j) o[i][j] *= corr[i];
        }

        __syncthreads();   // done reading Ks as K
        // write P into Ks buffer: [r][k], row-swizzled float4 stores
#pragma unroll
        for (int i = 0; i < 4; ++i) {
            *(float4*)&Ks[rq[i] * 64 + (((tx * 2)     ^ swQ[i]) << 2)] =
                make_float4(s[i][0], s[i][1], s[i][2], s[i][3]);
            *(float4*)&Ks[rq[i] * 64 + (((tx * 2 + 1) ^ swQ[i]) << 2)] =
                make_float4(s[i][4], s[i][5], s[i][6], s[i][7]);
        }
        __syncthreads();

        // O += P @ V, vectorized
#pragma unroll 4
        for (int kq = 0; kq < 16; ++kq) {
            float p[4][4];
#pragma unroll
            for (int i = 0; i < 4; ++i)
                *(float4*)p[i] = *(const float4*)&Ks[rq[i] * 64 + ((kq ^ swQ[i]) << 2)];
#pragma unroll
            for (int t = 0; t < 4; ++t) {
                int k = kq * 4 + t;
                float4 v0 = *(const float4*)&Vs[k * 64 + tx * 8];
                float4 v1 = *(const float4*)&Vs[k * 64 + tx * 8 + 4];
#pragma unroll
                for (int i = 0; i < 4; ++i) {
                    float pr = p[i][t];
                    o[i][0] = fmaf(pr, v0.x, o[i][0]);
                    o[i][1] = fmaf(pr, v0.y, o[i][1]);
                    o[i][2] = fmaf(pr, v0.z, o[i][2]);
                    o[i][3] = fmaf(pr, v0.w, o[i][3]);
                    o[i][4] = fmaf(pr, v1.x, o[i][4]);
                    o[i][5] = fmaf(pr, v1.y, o[i][5]);
                    o[i][6] = fmaf(pr, v1.z, o[i][6]);
                    o[i][7] = fmaf(pr, v1.w, o[i][7]);
                }
            }
        }
    }

    // epilogue: out[b][n][h*64 + d]
#pragma unroll
    for (int i = 0; i < 4; ++i) {
        float inv = 1.0f / l_i[i];
        int qr = qb * 64 + ty * 4 + i;
        float4 r0 = make_float4(o[i][0] * inv, o[i][1] * inv, o[i][2] * inv, o[i][3] * inv);
        float4 r1 = make_float4(o[i][4] * inv, o[i][5] * inv, o[i][6] * inv, o[i][7] * inv);
        float* dst = out + (size_t)(b * NN + qr) * DD + h * DH + tx * 8;
        *(float4*)(dst)     = r0;
        *(float4*)(dst + 4) = r1;
    }
}

// ---------------------------------------------------------------------------
extern "C" void kernel_launch(void* const* d_in, const int* in_sizes, int n_in,
                              void* d_out, int out_size)
{
    const float* x = (const float*)d_in[0];   // [2,2048,1024] fp32
    const float* w = (const float*)d_in[1];   // [1024,3072] fp32
    float* out = (float*)d_out;               // [2,2048,1024] fp32
    (void)in_sizes; (void)n_in; (void)out_size;

    // QKV projection into per-head scratch
    dim3 g1(D3 / 128, MM / 128);   // (24, 32)
    qkv_gemm_kernel<<<g1, 256>>>(x, w);

    // causal attention
    cudaFuncSetAttribute(attn_kernel,
                         cudaFuncAttributeMaxDynamicSharedMemorySize,
                         ATT_SMEM_BYTES);
    dim3 g2(NN / 64, HH, BB);      // (32, 16, 2)
    attn_kernel<<<g2, 128, ATT_SMEM_BYTES>>>(out);
}